// round 1
// baseline (speedup 1.0000x reference)
// PriorLayer online belief-propagation scan on GB300 (sm_103a).
//
// Algorithm: the recursion state_t = normalize(diag(p_t) @ T @ state_{t-1}) is
// scale-invariant (normalization is a scalar), so we run it UNNORMALIZED with a
// fixed 2^-6 per-step rescale, and normalize + compute entropy in a separate
// memory-bound post-pass. The chain forgets its initial condition exponentially
// (T ~ rank-1 dominant), so the sequence is split into 152 chunks processed in
// parallel, each warmed up W=64 steps before its output window from a uniform
// init (chunk 0 is exact, warmup error << fp32 eps).
//
// Kernels:
//   1. conv_kernel : T fp32 -> bf16 copy in __device__ global (L1-resident, 128KB)
//   2. scan_kernel : 152 CTAs x 512 threads; per step each thread does a
//                    2-row x 64-col slice of the matvec (bf16 T via LDG/L1,
//                    fp32 state in smem double buffer), 4-lane shfl reduce,
//                    multiply by p_t * 2^-6, write unnormalized row to d_out.
//   3. norm_kernel : warp-per-row normalize + entropy, in place.

#include <cuda_runtime.h>
#include <cuda_bf16.h>
#include <cstdint>

#define DIM     256
#define SEQ     65536
#define NCTA    152
#define WARMUP  64
#define THREADS 512
#define RESC    0.015625f   // 2^-6, cancels expected per-step growth (~64x)

// bf16 copy of transition_prior, row-major [i][j]. 128KB -> fits in L1.
__device__ __nv_bfloat16 g_Tbf[DIM * DIM];

__global__ void pl_conv_kernel(const float* __restrict__ T) {
    int i = blockIdx.x * blockDim.x + threadIdx.x;
    if (i < DIM * DIM) g_Tbf[i] = __float2bfloat16(T[i]);
}

// unpack bf16x2 (packed in u32) to two fp32 (pure alu-pipe ops)
__device__ __forceinline__ void bf16x2_to_f32(unsigned u, float& lo, float& hi) {
    lo = __uint_as_float(u << 16);           // element 2j   (low half)
    hi = __uint_as_float(u & 0xffff0000u);   // element 2j+1 (high half)
}

// state buffer padded: logical j -> physical j + (j>>6)*4 so that the four
// q-slices start 272B apart (distinct bank phases, no 4-way LDS conflict)
__device__ __forceinline__ int spad(int j) { return j + ((j >> 6) << 2); }

__global__ __launch_bounds__(THREADS)
void pl_scan_kernel(const float* __restrict__ probs, float* __restrict__ wout) {
    __shared__ float sbuf[2][DIM + 16];

    const int tid = threadIdx.x;
    const int q   = tid & 3;        // column slice: cols [q*64, q*64+64)
    const int h   = tid >> 2;       // rows h and h+128
    const int c   = blockIdx.x;

    const int L        = (SEQ + NCTA - 1) / NCTA;   // 432
    const int outStart = c * L;
    const int tEnd     = min(SEQ, outStart + L);
    const int t0       = max(0, outStart - WARMUP);

    // uniform init (any constant works — scale cancels in the post-pass;
    // chunk 0 is therefore exact)
    for (int i = tid; i < DIM + 16; i += THREADS) {
        sbuf[0][i] = 1.0f;
        sbuf[1][i] = 0.0f;
    }
    __syncthreads();

    // this thread's T slices: rows h and h+128, cols [q*64, q*64+64) as uint4 (8 bf16 each)
    const uint4* Tr0 = reinterpret_cast<const uint4*>(g_Tbf + h * DIM + q * 64);
    const uint4* Tr1 = reinterpret_cast<const uint4*>(g_Tbf + (h + 128) * DIM + q * 64);

    int cur = 0;
    // prefetch observation row for t0 (L2-only caching keeps L1 reserved for T)
    float pf0 = __ldcg(probs + (size_t)t0 * DIM + h) * RESC;
    float pf1 = __ldcg(probs + (size_t)t0 * DIM + h + 128) * RESC;

    for (int t = t0; t < tEnd; ++t) {
        const float p0 = pf0;
        const float p1 = pf1;
        const int tn = (t + 1 < tEnd) ? (t + 1) : t;
        pf0 = __ldcg(probs + (size_t)tn * DIM + h) * RESC;
        pf1 = __ldcg(probs + (size_t)tn * DIM + h + 128) * RESC;

        const float4* sv = reinterpret_cast<const float4*>(&sbuf[cur][q * 68]);

        float acc0 = 0.0f, acc1 = 0.0f;
        #pragma unroll
        for (int j = 0; j < 8; ++j) {          // 8 bf16 per row per iter
            const uint4 ta = __ldg(Tr0 + j);
            const uint4 tb = __ldg(Tr1 + j);
            const float4 sA = sv[2 * j];
            const float4 sB = sv[2 * j + 1];
            float f0, f1;
            bf16x2_to_f32(ta.x, f0, f1); acc0 += f0 * sA.x; acc0 += f1 * sA.y;
            bf16x2_to_f32(ta.y, f0, f1); acc0 += f0 * sA.z; acc0 += f1 * sA.w;
            bf16x2_to_f32(ta.z, f0, f1); acc0 += f0 * sB.x; acc0 += f1 * sB.y;
            bf16x2_to_f32(ta.w, f0, f1); acc0 += f0 * sB.z; acc0 += f1 * sB.w;
            bf16x2_to_f32(tb.x, f0, f1); acc1 += f0 * sA.x; acc1 += f1 * sA.y;
            bf16x2_to_f32(tb.y, f0, f1); acc1 += f0 * sA.z; acc1 += f1 * sA.w;
            bf16x2_to_f32(tb.z, f0, f1); acc1 += f0 * sB.x; acc1 += f1 * sB.y;
            bf16x2_to_f32(tb.w, f0, f1); acc1 += f0 * sB.z; acc1 += f1 * sB.w;
        }

        // sum the 4 q-partials (lanes 4k..4k+3 hold the same rows)
        acc0 += __shfl_xor_sync(0xffffffffu, acc0, 1);
        acc0 += __shfl_xor_sync(0xffffffffu, acc0, 2);
        acc1 += __shfl_xor_sync(0xffffffffu, acc1, 1);
        acc1 += __shfl_xor_sync(0xffffffffu, acc1, 2);

        const float v0 = acc0 * p0;
        const float v1 = acc1 * p1;

        const int nxt = cur ^ 1;
        if (q == 0) {
            sbuf[nxt][spad(h)]       = v0;
            sbuf[nxt][spad(h + 128)] = v1;
            if (t >= outStart) {
                wout[(size_t)t * DIM + h]       = v0;
                wout[(size_t)t * DIM + h + 128] = v1;
            }
        }
        __syncthreads();   // next state fully written; double buffer -> 1 sync/step
        cur = nxt;
    }
}

// warp-per-row: normalize in place + entropy
__global__ void pl_norm_kernel(float* __restrict__ w, float* __restrict__ unc) {
    const int warp = (blockIdx.x * blockDim.x + threadIdx.x) >> 5;
    const int lane = threadIdx.x & 31;
    if (warp >= SEQ) return;

    float* row = w + (size_t)warp * DIM;
    float4 a = *reinterpret_cast<const float4*>(row + lane * 8);
    float4 b = *reinterpret_cast<const float4*>(row + lane * 8 + 4);

    float s = a.x + a.y + a.z + a.w + b.x + b.y + b.z + b.w;
    #pragma unroll
    for (int m = 16; m; m >>= 1) s += __shfl_xor_sync(0xffffffffu, s, m);

    const float inv = 1.0f / s;
    a.x *= inv; a.y *= inv; a.z *= inv; a.w *= inv;
    b.x *= inv; b.y *= inv; b.z *= inv; b.w *= inv;

    float e = 0.0f;
    e -= a.x * __logf(a.x + 1e-10f);
    e -= a.y * __logf(a.y + 1e-10f);
    e -= a.z * __logf(a.z + 1e-10f);
    e -= a.w * __logf(a.w + 1e-10f);
    e -= b.x * __logf(b.x + 1e-10f);
    e -= b.y * __logf(b.y + 1e-10f);
    e -= b.z * __logf(b.z + 1e-10f);
    e -= b.w * __logf(b.w + 1e-10f);

    *reinterpret_cast<float4*>(row + lane * 8)     = a;
    *reinterpret_cast<float4*>(row + lane * 8 + 4) = b;

    #pragma unroll
    for (int m = 16; m; m >>= 1) e += __shfl_xor_sync(0xffffffffu, e, m);
    if (lane == 0) unc[warp] = e;
}

extern "C" void kernel_launch(void* const* d_in, const int* in_sizes, int n_in,
                              void* d_out, int out_size) {
    const float* probs = (const float*)d_in[0];          // (SEQ, DIM)
    const float* T     = (const float*)d_in[1];          // (DIM, DIM)
    float* out  = (float*)d_out;                         // probs region
    float* unc  = out + (size_t)SEQ * DIM;               // uncertainty region

    pl_conv_kernel<<<DIM * DIM / 256, 256>>>(T);
    pl_scan_kernel<<<NCTA, THREADS>>>(probs, out);
    pl_norm_kernel<<<(SEQ * 32) / 256, 256>>>(out, unc); // 8 rows per 256-thread block
}

// round 3
// speedup vs baseline: 6.5206x; 6.5206x over previous
// PriorLayer online belief-propagation scan on GB300 (sm_103a) — mma.sync version.
//
// NOTE: the harness compiles via a compute_103 (non-'a') virtual arch, so
// tcgen05/TMEM PTX is unavailable (arch-accelerated features). We use warp-level
// mma.sync.m16n8k16 bf16 (sm_80+ PTX) instead.
//
// Algorithm: state_t = normalize(diag(p_t) @ T @ state_{t-1}) is scale-invariant,
// so the recursion runs UNNORMALIZED with a fixed 2^-6 rescale; a memory-bound
// post-pass normalizes and computes entropy. The chain forgets its initial
// condition at ~10x/step (T is rank-1 dominant), so the sequence splits into
// 4736 chunks (148 CTAs x 32 columns), each warmed up WARM=16 steps from a
// uniform init (chunk 0 exact: state forced uniform while t<0).
//
// Per CTA per step: D(256x32) = T(256x256,bf16,smem) @ V(256x32,bf16,smem).
// 8 warps; warp w owns rows 32w..32w+31. Per warp: 16 k-tiles x (2 ldmatrix.x4 A
// + 2 ldmatrix.x4.trans B + 8 HMMA.16816). T rows padded to 528B and V rows to
// 80B so every ldmatrix phase hits 8 distinct 16B bank-phases (conflict-free).
// V double-buffered -> exactly one __syncthreads per step.

#include <cuda_runtime.h>
#include <cuda_bf16.h>
#include <cstdint>

#define DIM     256
#define SEQ     65536
#define NCTA    148
#define NCOL    32                 // chunk columns per CTA
#define LCH     14                 // output steps per chunk (148*32*14 >= 65536)
#define WARM    16
#define STEPS   (WARM + LCH)       // 30
#define THREADS 256
#define RESC    0.015625f          // 2^-6 cancels expected per-step growth (~64x)

#define PT_B    528                // T smem row stride in bytes (256 bf16 + 8 pad)
#define PV_B    80                 // V smem row stride in bytes (32 bf16 + 8 pad)
#define T_BYTES (DIM * PT_B)       // 135168
#define V_BYTES (DIM * PV_B)       // 20480 per buffer
#define SMEM_BYTES (T_BYTES + 2 * V_BYTES)

__device__ __forceinline__ uint32_t smem_u32(const void* p) {
    uint32_t a;
    asm("{ .reg .u64 t; cvta.to.shared.u64 t, %1; cvt.u32.u64 %0, t; }" : "=r"(a) : "l"(p));
    return a;
}

#define LDSM_X4(r, addr) \
    asm volatile("ldmatrix.sync.aligned.m8n8.x4.shared.b16 {%0,%1,%2,%3}, [%4];" \
                 : "=r"((r)[0]), "=r"((r)[1]), "=r"((r)[2]), "=r"((r)[3]) : "r"(addr))
#define LDSM_X4_T(r, addr) \
    asm volatile("ldmatrix.sync.aligned.m8n8.x4.trans.shared.b16 {%0,%1,%2,%3}, [%4];" \
                 : "=r"((r)[0]), "=r"((r)[1]), "=r"((r)[2]), "=r"((r)[3]) : "r"(addr))
#define MMA16816(c, a, bb0, bb1) \
    asm volatile("mma.sync.aligned.m16n8k16.row.col.f32.bf16.bf16.f32 " \
                 "{%0,%1,%2,%3}, {%4,%5,%6,%7}, {%8,%9}, {%0,%1,%2,%3};" \
                 : "+f"((c)[0]), "+f"((c)[1]), "+f"((c)[2]), "+f"((c)[3]) \
                 : "r"((a)[0]), "r"((a)[1]), "r"((a)[2]), "r"((a)[3]), "r"(bb0), "r"(bb1))

__global__ __launch_bounds__(THREADS, 1)
void pl_scan_mma(const float* __restrict__ probs, float* __restrict__ wout,
                 const float* __restrict__ T) {
    extern __shared__ char sm[];
    char* Tsm = sm;                    // bf16 T, row-major, 528B row stride
    char* Vsm = sm + T_BYTES;          // bf16 V[k][n] k-major, 80B rows, x2 buffers

    const int tid  = threadIdx.x;
    const int w    = tid >> 5;
    const int lane = tid & 31;
    const int g    = lane >> 2;        // group row  (0..7)
    const int q    = lane & 3;         // col pair   (0..3)
    const int g0   = blockIdx.x * NCOL;

    // ---- T: fp32 gmem -> bf16 smem (padded rows) ----
    for (int idx = tid; idx < DIM * DIM / 4; idx += THREADS) {
        int e = idx * 4;
        int i = e >> 8;                // row
        int k = e & 255;               // col (multiple of 4)
        float4 tv = *reinterpret_cast<const float4*>(T + i * DIM + k);
        __nv_bfloat162* dst = reinterpret_cast<__nv_bfloat162*>(Tsm + i * PT_B + k * 2);
        dst[0] = __floats2bfloat162_rn(tv.x, tv.y);
        dst[1] = __floats2bfloat162_rn(tv.z, tv.w);
    }
    // ---- V buffer 0: uniform state (bf16 1.0) ----
    for (int idx = tid; idx < V_BYTES / 4; idx += THREADS)
        *reinterpret_cast<uint32_t*>(Vsm + idx * 4) = 0x3F803F80u;
    __syncthreads();

    // ldmatrix lane address components
    const int mloc = ((lane >> 3) & 1) * 8 + (lane & 7);   // row within 16-row tile
    const int kofB = (lane >> 4) * 16;                     // 8-elem col block (bytes)
    // A base addresses (per m-tile), k advances by 32B per k-tile
    uint32_t aA[2];
    aA[0] = smem_u32(Tsm) + (w * 32 + 0  + mloc) * PT_B + kofB;
    aA[1] = smem_u32(Tsm) + (w * 32 + 16 + mloc) * PT_B + kofB;
    // B lane offset within a buffer (per n-half), k advances by 16*PV_B per k-tile
    const uint32_t bOff0 = (uint32_t)(mloc * PV_B + (lane >> 4) * 16);
    const uint32_t bOff1 = bOff0 + 32;                      // n-half 1 (+16 elems)
    const uint32_t vBase = smem_u32(Vsm);

    for (int step = 0; step < STEPS; ++step) {
        const int cur   = step & 1;
        const int tbase = step - WARM;
        const uint32_t bCur = vBase + cur * V_BYTES;
        const uint32_t bNxt = vBase + (cur ^ 1) * V_BYTES;

        // ---- observation gather (independent of MMA; issues early, hides latency)
        float pr[2][4][4];
        #pragma unroll
        for (int mt = 0; mt < 2; ++mt) {
            const int m0 = w * 32 + mt * 16 + g;
            #pragma unroll
            for (int nt = 0; nt < 4; ++nt) {
                #pragma unroll
                for (int j = 0; j < 2; ++j) {
                    int t  = (g0 + nt * 8 + q * 2 + j) * LCH + tbase;
                    int tc = min(max(t, 0), SEQ - 1);
                    const float* pp = probs + (size_t)tc * DIM + m0;
                    pr[mt][nt][j]     = __ldcg(pp)     * RESC;
                    pr[mt][nt][2 + j] = __ldcg(pp + 8) * RESC;
                }
            }
        }

        // ---- GEMM: D = T @ V ----
        float acc[2][4][4];
        #pragma unroll
        for (int mt = 0; mt < 2; ++mt)
            #pragma unroll
            for (int nt = 0; nt < 4; ++nt)
                #pragma unroll
                for (int i = 0; i < 4; ++i) acc[mt][nt][i] = 0.0f;

        #pragma unroll
        for (int kt = 0; kt < 16; ++kt) {
            uint32_t a0[4], a1[4], b0[4], b1[4];
            LDSM_X4(a0, aA[0] + kt * 32);
            LDSM_X4(a1, aA[1] + kt * 32);
            LDSM_X4_T(b0, bCur + bOff0 + kt * 16 * PV_B);
            LDSM_X4_T(b1, bCur + bOff1 + kt * 16 * PV_B);
            MMA16816(acc[0][0], a0, b0[0], b0[1]);
            MMA16816(acc[0][1], a0, b0[2], b0[3]);
            MMA16816(acc[0][2], a0, b1[0], b1[1]);
            MMA16816(acc[0][3], a0, b1[2], b1[3]);
            MMA16816(acc[1][0], a1, b0[0], b0[1]);
            MMA16816(acc[1][1], a1, b0[2], b0[3]);
            MMA16816(acc[1][2], a1, b1[0], b1[1]);
            MMA16816(acc[1][3], a1, b1[2], b1[3]);
        }

        // ---- epilogue: v = D*p (forced 1.0 pre-sequence), store output + next V
        #pragma unroll
        for (int mt = 0; mt < 2; ++mt) {
            const int m0 = w * 32 + mt * 16 + g;
            #pragma unroll
            for (int nt = 0; nt < 4; ++nt) {
                const int n0 = nt * 8 + q * 2;
                float v[4];
                #pragma unroll
                for (int j = 0; j < 2; ++j) {
                    const int t = (g0 + n0 + j) * LCH + tbase;
                    float v0 = acc[mt][nt][j]     * pr[mt][nt][j];
                    float v1 = acc[mt][nt][2 + j] * pr[mt][nt][2 + j];
                    if (t < 0) { v0 = 1.0f; v1 = 1.0f; }     // chunk 0 pre-window
                    if (tbase >= 0 && t < SEQ) {
                        wout[(size_t)t * DIM + m0]     = v0; // unnormalized
                        wout[(size_t)t * DIM + m0 + 8] = v1;
                    }
                    v[j] = v0; v[2 + j] = v1;
                }
                // next-state V (bf16): rows k=m0 and k=m0+8, col pair (n0, n0+1)
                __nv_bfloat162 lo = __floats2bfloat162_rn(v[0], v[1]);
                __nv_bfloat162 hi = __floats2bfloat162_rn(v[2], v[3]);
                asm volatile("st.shared.b32 [%0], %1;" ::
                    "r"(bNxt + (uint32_t)(m0 * PV_B + n0 * 2)),
                    "r"(*reinterpret_cast<uint32_t*>(&lo)));
                asm volatile("st.shared.b32 [%0], %1;" ::
                    "r"(bNxt + (uint32_t)((m0 + 8) * PV_B + n0 * 2)),
                    "r"(*reinterpret_cast<uint32_t*>(&hi)));
            }
        }
        __syncthreads();   // next V fully written; double buffer -> 1 sync/step
    }
}

// warp-per-row: normalize in place + entropy
__global__ void pl_norm_kernel(float* __restrict__ w, float* __restrict__ unc) {
    const int warp = (blockIdx.x * blockDim.x + threadIdx.x) >> 5;
    const int lane = threadIdx.x & 31;
    if (warp >= SEQ) return;

    float* row = w + (size_t)warp * DIM;
    float4 a = *reinterpret_cast<const float4*>(row + lane * 8);
    float4 b = *reinterpret_cast<const float4*>(row + lane * 8 + 4);

    float s = a.x + a.y + a.z + a.w + b.x + b.y + b.z + b.w;
    #pragma unroll
    for (int m = 16; m; m >>= 1) s += __shfl_xor_sync(0xffffffffu, s, m);

    const float inv = 1.0f / s;
    a.x *= inv; a.y *= inv; a.z *= inv; a.w *= inv;
    b.x *= inv; b.y *= inv; b.z *= inv; b.w *= inv;

    float e = 0.0f;
    e -= a.x * __logf(a.x + 1e-10f);
    e -= a.y * __logf(a.y + 1e-10f);
    e -= a.z * __logf(a.z + 1e-10f);
    e -= a.w * __logf(a.w + 1e-10f);
    e -= b.x * __logf(b.x + 1e-10f);
    e -= b.y * __logf(b.y + 1e-10f);
    e -= b.z * __logf(b.z + 1e-10f);
    e -= b.w * __logf(b.w + 1e-10f);

    *reinterpret_cast<float4*>(row + lane * 8)     = a;
    *reinterpret_cast<float4*>(row + lane * 8 + 4) = b;

    #pragma unroll
    for (int m = 16; m; m >>= 1) e += __shfl_xor_sync(0xffffffffu, e, m);
    if (lane == 0) unc[warp] = e;
}

extern "C" void kernel_launch(void* const* d_in, const int* in_sizes, int n_in,
                              void* d_out, int out_size) {
    const float* probs = (const float*)d_in[0];          // (SEQ, DIM)
    const float* T     = (const float*)d_in[1];          // (DIM, DIM)
    float* out = (float*)d_out;                          // probs region
    float* unc = out + (size_t)SEQ * DIM;                // uncertainty region

    cudaFuncSetAttribute(pl_scan_mma, cudaFuncAttributeMaxDynamicSharedMemorySize, SMEM_BYTES);
    pl_scan_mma<<<NCTA, THREADS, SMEM_BYTES>>>(probs, out, T);
    pl_norm_kernel<<<(SEQ * 32) / 256, 256>>>(out, unc);
}

// round 4
// speedup vs baseline: 8.7147x; 1.3365x over previous
// PriorLayer online belief-propagation scan on GB300 (sm_103a) — fused mma.sync version.
//
// (tcgen05 unavailable: harness compiles via compute_103 virtual arch, which
// rejects arch-accelerated PTX. Warp-level mma.sync.m16n8k16 bf16 instead.)
//
// state_t = normalize(diag(p_t) @ T @ state_{t-1}) is scale-invariant -> run
// UNNORMALIZED with fixed 2^-6 rescale. Chain contracts ~14x/step (T rank-1
// dominant) -> 4736 chunks (148 CTAs x 32 cols), WARM=8 warmup steps from
// uniform (error ~14^-8 ~ 7e-10; chunk 0 exact via forced-uniform t<0).
//
// Per CTA per step: D(256x32) = T(256x256,bf16,smem) @ V(256x32,bf16,smem),
// 16 warps x (1 m-tile of 16 rows x 16 k-tiles x 4 HMMA.16816). T rows padded
// to 528B, V rows to 80B (all ldmatrix phases conflict-free). V double-buffered.
// Output steps fuse normalization + entropy via two smem CTA reductions, so no
// separate post-pass and half the DRAM traffic.

#include <cuda_runtime.h>
#include <cuda_bf16.h>
#include <cstdint>

#define DIM     256
#define SEQ     65536
#define NCTA    148
#define NCOL    32                 // chunk columns per CTA
#define LCH     14                 // output steps per chunk (148*32*14 >= 65536)
#define WARM    8
#define STEPS   (WARM + LCH)       // 22
#define THREADS 512
#define NW      16                 // warps
#define RESC    0.015625f          // 2^-6 cancels expected per-step growth (~64x)

#define PT_B    528                // T smem row stride (256 bf16 + 8 pad)
#define PV_B    80                 // V smem row stride (32 bf16 + 8 pad)
#define T_BYTES (DIM * PT_B)       // 135168
#define V_BYTES (DIM * PV_B)       // 20480 per buffer
#define RED_OFF (T_BYTES + 2 * V_BYTES)
#define SMEM_BYTES (RED_OFF + (NW * NCOL * 2 + NCOL) * 4)   // + partial/epart/sInv

__device__ __forceinline__ uint32_t smem_u32(const void* p) {
    uint32_t a;
    asm("{ .reg .u64 t; cvta.to.shared.u64 t, %1; cvt.u32.u64 %0, t; }" : "=r"(a) : "l"(p));
    return a;
}

#define LDSM_X4(r, addr) \
    asm volatile("ldmatrix.sync.aligned.m8n8.x4.shared.b16 {%0,%1,%2,%3}, [%4];" \
                 : "=r"((r)[0]), "=r"((r)[1]), "=r"((r)[2]), "=r"((r)[3]) : "r"(addr))
#define LDSM_X4_T(r, addr) \
    asm volatile("ldmatrix.sync.aligned.m8n8.x4.trans.shared.b16 {%0,%1,%2,%3}, [%4];" \
                 : "=r"((r)[0]), "=r"((r)[1]), "=r"((r)[2]), "=r"((r)[3]) : "r"(addr))
#define MMA16816(c, a, bb0, bb1) \
    asm volatile("mma.sync.aligned.m16n8k16.row.col.f32.bf16.bf16.f32 " \
                 "{%0,%1,%2,%3}, {%4,%5,%6,%7}, {%8,%9}, {%0,%1,%2,%3};" \
                 : "+f"((c)[0]), "+f"((c)[1]), "+f"((c)[2]), "+f"((c)[3]) \
                 : "r"((a)[0]), "r"((a)[1]), "r"((a)[2]), "r"((a)[3]), "r"(bb0), "r"(bb1))

__global__ __launch_bounds__(THREADS, 1)
void pl_scan_fused(const float* __restrict__ probs, float* __restrict__ wout,
                   float* __restrict__ unc, const float* __restrict__ T) {
    extern __shared__ char sm[];
    char*  Tsm     = sm;                                   // bf16 T, 528B rows
    char*  Vsm     = sm + T_BYTES;                         // bf16 V x2 buffers
    float* partial = reinterpret_cast<float*>(sm + RED_OFF);        // [NW][NCOL]
    float* epart   = partial + NW * NCOL;                           // [NW][NCOL]
    float* sInv    = epart + NW * NCOL;                             // [NCOL]

    const int tid  = threadIdx.x;
    const int w    = tid >> 5;
    const int lane = tid & 31;
    const int g    = (lane >> 2) & 7;  // row within 8-group
    const int q    = lane & 3;         // col pair
    const int m0   = w * 16 + g;       // this thread's first output row
    const int g0   = blockIdx.x * NCOL;

    // ---- T: fp32 gmem -> bf16 smem (padded rows) ----
    for (int idx = tid; idx < DIM * DIM / 4; idx += THREADS) {
        int e = idx * 4;
        int i = e >> 8;
        int k = e & 255;
        float4 tv = *reinterpret_cast<const float4*>(T + i * DIM + k);
        __nv_bfloat162* dst = reinterpret_cast<__nv_bfloat162*>(Tsm + i * PT_B + k * 2);
        dst[0] = __floats2bfloat162_rn(tv.x, tv.y);
        dst[1] = __floats2bfloat162_rn(tv.z, tv.w);
    }
    // ---- V buffer 0: uniform state ----
    for (int idx = tid; idx < V_BYTES / 4; idx += THREADS)
        *reinterpret_cast<uint32_t*>(Vsm + idx * 4) = 0x3F803F80u;
    __syncthreads();

    // ldmatrix lane addressing (same recipe as validated R3 kernel)
    const int mloc = ((lane >> 3) & 1) * 8 + (lane & 7);
    const int kofB = (lane >> 4) * 16;
    const uint32_t aBase = smem_u32(Tsm) + (w * 16 + mloc) * PT_B + kofB;
    const uint32_t bOff0 = (uint32_t)(mloc * PV_B + (lane >> 4) * 16);
    const uint32_t bOff1 = bOff0 + 32;
    const uint32_t vBase = smem_u32(Vsm);

    for (int step = 0; step < STEPS; ++step) {
        const int cur   = step & 1;
        const int tbase = step - WARM;
        const uint32_t bCur = vBase + cur * V_BYTES;
        const uint32_t bNxt = vBase + (cur ^ 1) * V_BYTES;

        // ---- observation gather (issues early; consumed in epilogue) ----
        float pr[4][2][2];
        #pragma unroll
        for (int nt = 0; nt < 4; ++nt)
            #pragma unroll
            for (int j = 0; j < 2; ++j) {
                int t  = (g0 + nt * 8 + q * 2 + j) * LCH + tbase;
                int tc = min(max(t, 0), SEQ - 1);
                const float* pp = probs + (size_t)tc * DIM + m0;
                pr[nt][j][0] = __ldcg(pp)     * RESC;
                pr[nt][j][1] = __ldcg(pp + 8) * RESC;
            }

        // ---- GEMM: this warp's 16 rows x all 32 cols ----
        float acc[4][4];
        #pragma unroll
        for (int nt = 0; nt < 4; ++nt)
            #pragma unroll
            for (int i = 0; i < 4; ++i) acc[nt][i] = 0.0f;

        #pragma unroll
        for (int kt = 0; kt < 16; ++kt) {
            uint32_t a[4], b0[4], b1[4];
            LDSM_X4(a, aBase + kt * 32);
            LDSM_X4_T(b0, bCur + bOff0 + kt * 16 * PV_B);
            LDSM_X4_T(b1, bCur + bOff1 + kt * 16 * PV_B);
            MMA16816(acc[0], a, b0[0], b0[1]);
            MMA16816(acc[1], a, b0[2], b0[3]);
            MMA16816(acc[2], a, b1[0], b1[1]);
            MMA16816(acc[3], a, b1[2], b1[3]);
        }

        // ---- unnormalized next state; write bf16 V for next step ----
        float vv[4][2][2];
        #pragma unroll
        for (int nt = 0; nt < 4; ++nt) {
            const int n0 = nt * 8 + q * 2;
            #pragma unroll
            for (int j = 0; j < 2; ++j) {
                const int t = (g0 + n0 + j) * LCH + tbase;
                float v0 = acc[nt][j]     * pr[nt][j][0];
                float v1 = acc[nt][2 + j] * pr[nt][j][1];
                if (t < 0) { v0 = 1.0f; v1 = 1.0f; }   // chunk 0 pre-window
                vv[nt][j][0] = v0;
                vv[nt][j][1] = v1;
            }
            __nv_bfloat162 lo = __floats2bfloat162_rn(vv[nt][0][0], vv[nt][1][0]);
            __nv_bfloat162 hi = __floats2bfloat162_rn(vv[nt][0][1], vv[nt][1][1]);
            asm volatile("st.shared.b32 [%0], %1;" ::
                "r"(bNxt + (uint32_t)(m0 * PV_B + n0 * 2)),
                "r"(*reinterpret_cast<uint32_t*>(&lo)));
            asm volatile("st.shared.b32 [%0], %1;" ::
                "r"(bNxt + (uint32_t)((m0 + 8) * PV_B + n0 * 2)),
                "r"(*reinterpret_cast<uint32_t*>(&hi)));
        }

        if (tbase < 0) {            // warmup step: state update only
            __syncthreads();
            continue;
        }

        // ---- fused normalization: reduction 1 (sum over 256 dims per col) ----
        #pragma unroll
        for (int nt = 0; nt < 4; ++nt)
            #pragma unroll
            for (int j = 0; j < 2; ++j) {
                float s = vv[nt][j][0] + vv[nt][j][1];
                s += __shfl_xor_sync(0xffffffffu, s, 4);
                s += __shfl_xor_sync(0xffffffffu, s, 8);
                s += __shfl_xor_sync(0xffffffffu, s, 16);
                if (g == 0) partial[w * NCOL + nt * 8 + q * 2 + j] = s;
            }
        __syncthreads();
        if (tid < NCOL) {
            float tot = 0.0f;
            #pragma unroll
            for (int w2 = 0; w2 < NW; ++w2) tot += partial[w2 * NCOL + tid];
            sInv[tid] = 1.0f / tot;
        }
        __syncthreads();

        // ---- normalize + store output + entropy partials ----
        #pragma unroll
        for (int nt = 0; nt < 4; ++nt)
            #pragma unroll
            for (int j = 0; j < 2; ++j) {
                const int n = nt * 8 + q * 2 + j;
                const int t = (g0 + n) * LCH + tbase;
                const float inv = sInv[n];
                const float p0 = vv[nt][j][0] * inv;
                const float p1 = vv[nt][j][1] * inv;
                if (t < SEQ) {
                    wout[(size_t)t * DIM + m0]     = p0;
                    wout[(size_t)t * DIM + m0 + 8] = p1;
                }
                float e = p0 * __logf(p0 + 1e-10f) + p1 * __logf(p1 + 1e-10f);
                e += __shfl_xor_sync(0xffffffffu, e, 4);
                e += __shfl_xor_sync(0xffffffffu, e, 8);
                e += __shfl_xor_sync(0xffffffffu, e, 16);
                if (g == 0) epart[w * NCOL + n] = e;
            }
        __syncthreads();            // also protects bNxt for next step
        if (tid < NCOL) {
            float e = 0.0f;
            #pragma unroll
            for (int w2 = 0; w2 < NW; ++w2) e += epart[w2 * NCOL + tid];
            const int tg = (g0 + tid) * LCH + tbase;
            if (tg < SEQ) unc[tg] = -e;
        }
    }
}

extern "C" void kernel_launch(void* const* d_in, const int* in_sizes, int n_in,
                              void* d_out, int out_size) {
    const float* probs = (const float*)d_in[0];          // (SEQ, DIM)
    const float* T     = (const float*)d_in[1];          // (DIM, DIM)
    float* out = (float*)d_out;                          // normalized probs
    float* unc = out + (size_t)SEQ * DIM;                // entropy

    cudaFuncSetAttribute(pl_scan_fused, cudaFuncAttributeMaxDynamicSharedMemorySize, SMEM_BYTES);
    pl_scan_fused<<<NCTA, THREADS, SMEM_BYTES>>>(probs, out, unc, T);
}

// round 5
// speedup vs baseline: 10.0165x; 1.1494x over previous
// PriorLayer online belief-propagation scan on GB300 (sm_103a) — fused mma.sync,
// A-resident-in-registers version.
//
// (tcgen05 unavailable: harness compiles via compute_103 virtual arch which
// rejects arch-accelerated PTX. Warp-level mma.sync.m16n8k16 bf16 instead.)
//
// state_t = normalize(diag(p_t) @ T @ state_{t-1}) is scale-invariant -> run
// UNNORMALIZED with fixed 2^-6 rescale. Chain contracts ~14x/step (T rank-1
// dominant) -> 4736 chunks (148 CTAs x 32 cols), WARM=6 warmup steps from
// uniform (error ~1e-7; chunk 0 exact via forced-uniform t<0).
//
// Per CTA per step: D(256x32) = T(256x256,bf16) @ V(256x32,bf16,smem).
// 16 warps; warp w owns rows 16w..16w+15. T fragments are hoisted ONCE into
// 64 persistent registers/thread (16 k-tiles x 4 regs) in a prologue; the
// steady-state step touches smem only for V (ldmatrix.x4.trans) + reductions.
// V rows padded to 80B (conflict-free), double-buffered, one sync per warmup
// step. Output steps fuse normalization + entropy via two smem reductions.

#include <cuda_runtime.h>
#include <cuda_bf16.h>
#include <cstdint>

#define DIM     256
#define SEQ     65536
#define NCTA    148
#define NCOL    32                 // chunk columns per CTA
#define LCH     14                 // output steps per chunk (148*32*14 >= 65536)
#define WARM    6
#define STEPS   (WARM + LCH)       // 20
#define THREADS 512
#define NW      16                 // warps
#define RESC    0.015625f          // 2^-6 cancels expected per-step growth (~64x)

#define PT_B    528                // T smem row stride (prologue only)
#define PV_B    80                 // V smem row stride (32 bf16 + 8 pad)
#define T_BYTES (DIM * PT_B)       // 135168
#define V_BYTES (DIM * PV_B)       // 20480 per buffer
#define RED_OFF (T_BYTES + 2 * V_BYTES)
#define SMEM_BYTES (RED_OFF + (NW * NCOL * 2 + NCOL) * 4)

__device__ __forceinline__ uint32_t smem_u32(const void* p) {
    uint32_t a;
    asm("{ .reg .u64 t; cvta.to.shared.u64 t, %1; cvt.u32.u64 %0, t; }" : "=r"(a) : "l"(p));
    return a;
}

#define LDSM_X4(r, addr) \
    asm volatile("ldmatrix.sync.aligned.m8n8.x4.shared.b16 {%0,%1,%2,%3}, [%4];" \
                 : "=r"((r)[0]), "=r"((r)[1]), "=r"((r)[2]), "=r"((r)[3]) : "r"(addr))
#define LDSM_X4_T(r, addr) \
    asm volatile("ldmatrix.sync.aligned.m8n8.x4.trans.shared.b16 {%0,%1,%2,%3}, [%4];" \
                 : "=r"((r)[0]), "=r"((r)[1]), "=r"((r)[2]), "=r"((r)[3]) : "r"(addr))
#define MMA16816(c, a, bb0, bb1) \
    asm volatile("mma.sync.aligned.m16n8k16.row.col.f32.bf16.bf16.f32 " \
                 "{%0,%1,%2,%3}, {%4,%5,%6,%7}, {%8,%9}, {%0,%1,%2,%3};" \
                 : "+f"((c)[0]), "+f"((c)[1]), "+f"((c)[2]), "+f"((c)[3]) \
                 : "r"((a)[0]), "r"((a)[1]), "r"((a)[2]), "r"((a)[3]), "r"(bb0), "r"(bb1))

__global__ __launch_bounds__(THREADS, 1)
void pl_scan_fused(const float* __restrict__ probs, float* __restrict__ wout,
                   float* __restrict__ unc, const float* __restrict__ T) {
    extern __shared__ char sm[];
    char*  Tsm     = sm;                                   // prologue only
    char*  Vsm     = sm + T_BYTES;                         // bf16 V x2 buffers
    float* partial = reinterpret_cast<float*>(sm + RED_OFF);        // [NW][NCOL]
    float* epart   = partial + NW * NCOL;                           // [NW][NCOL]
    float* sInv    = epart + NW * NCOL;                             // [NCOL]

    const int tid  = threadIdx.x;
    const int w    = tid >> 5;
    const int lane = tid & 31;
    const int g    = (lane >> 2) & 7;  // row within 8-group
    const int q    = lane & 3;         // col pair
    const int m0   = w * 16 + g;       // this thread's first output row
    const int g0   = blockIdx.x * NCOL;

    // ---- prologue: T fp32 -> bf16 smem (padded rows) ----
    for (int idx = tid; idx < DIM * DIM / 4; idx += THREADS) {
        int e = idx * 4;
        int i = e >> 8;
        int k = e & 255;
        float4 tv = *reinterpret_cast<const float4*>(T + i * DIM + k);
        __nv_bfloat162* dst = reinterpret_cast<__nv_bfloat162*>(Tsm + i * PT_B + k * 2);
        dst[0] = __floats2bfloat162_rn(tv.x, tv.y);
        dst[1] = __floats2bfloat162_rn(tv.z, tv.w);
    }
    for (int idx = tid; idx < V_BYTES / 4; idx += THREADS)
        *reinterpret_cast<uint32_t*>(Vsm + idx * 4) = 0x3F803F80u;   // uniform V0
    __syncthreads();

    // ---- hoist A fragments into persistent registers (T never changes) ----
    const int mloc = ((lane >> 3) & 1) * 8 + (lane & 7);
    const int kofB = (lane >> 4) * 16;
    const uint32_t aBase = smem_u32(Tsm) + (w * 16 + mloc) * PT_B + kofB;
    uint32_t aF[16][4];
    #pragma unroll
    for (int kt = 0; kt < 16; ++kt) LDSM_X4(aF[kt], aBase + kt * 32);

    const uint32_t bOff0 = (uint32_t)(mloc * PV_B + (lane >> 4) * 16);
    const uint32_t bOff1 = bOff0 + 32;
    const uint32_t vBase = smem_u32(Vsm);

    for (int step = 0; step < STEPS; ++step) {
        const int cur   = step & 1;
        const int tbase = step - WARM;
        const uint32_t bCur = vBase + cur * V_BYTES;
        const uint32_t bNxt = vBase + (cur ^ 1) * V_BYTES;

        // ---- observation gather (issues early; consumed after MMA) ----
        float pr[4][2][2];
        #pragma unroll
        for (int nt = 0; nt < 4; ++nt)
            #pragma unroll
            for (int j = 0; j < 2; ++j) {
                int t  = (g0 + nt * 8 + q * 2 + j) * LCH + tbase;
                int tc = min(max(t, 0), SEQ - 1);
                const float* pp = probs + (size_t)tc * DIM + m0;
                pr[nt][j][0] = __ldcg(pp)     * RESC;
                pr[nt][j][1] = __ldcg(pp + 8) * RESC;
            }

        // ---- GEMM: this warp's 16 rows x all 32 cols (A from registers) ----
        float acc[4][4];
        #pragma unroll
        for (int nt = 0; nt < 4; ++nt)
            #pragma unroll
            for (int i = 0; i < 4; ++i) acc[nt][i] = 0.0f;

        #pragma unroll
        for (int kt = 0; kt < 16; ++kt) {
            uint32_t b0[4], b1[4];
            LDSM_X4_T(b0, bCur + bOff0 + kt * 16 * PV_B);
            LDSM_X4_T(b1, bCur + bOff1 + kt * 16 * PV_B);
            MMA16816(acc[0], aF[kt], b0[0], b0[1]);
            MMA16816(acc[1], aF[kt], b0[2], b0[3]);
            MMA16816(acc[2], aF[kt], b1[0], b1[1]);
            MMA16816(acc[3], aF[kt], b1[2], b1[3]);
        }

        // ---- apply observation (in place), write bf16 V for next step ----
        #pragma unroll
        for (int nt = 0; nt < 4; ++nt) {
            const int n0 = nt * 8 + q * 2;
            #pragma unroll
            for (int j = 0; j < 2; ++j) {
                const int t = (g0 + n0 + j) * LCH + tbase;
                float v0 = acc[nt][j]     * pr[nt][j][0];
                float v1 = acc[nt][2 + j] * pr[nt][j][1];
                if (t < 0) { v0 = 1.0f; v1 = 1.0f; }   // chunk 0 pre-window
                acc[nt][j]     = v0;
                acc[nt][2 + j] = v1;
            }
            __nv_bfloat162 lo = __floats2bfloat162_rn(acc[nt][0], acc[nt][1]);
            __nv_bfloat162 hi = __floats2bfloat162_rn(acc[nt][2], acc[nt][3]);
            asm volatile("st.shared.b32 [%0], %1;" ::
                "r"(bNxt + (uint32_t)(m0 * PV_B + n0 * 2)),
                "r"(*reinterpret_cast<uint32_t*>(&lo)));
            asm volatile("st.shared.b32 [%0], %1;" ::
                "r"(bNxt + (uint32_t)((m0 + 8) * PV_B + n0 * 2)),
                "r"(*reinterpret_cast<uint32_t*>(&hi)));
        }

        if (tbase < 0) {            // warmup step: state update only
            __syncthreads();
            continue;
        }

        // ---- fused normalization: per-column sum over 256 dims ----
        #pragma unroll
        for (int nt = 0; nt < 4; ++nt)
            #pragma unroll
            for (int j = 0; j < 2; ++j) {
                float s = acc[nt][j] + acc[nt][2 + j];
                s += __shfl_xor_sync(0xffffffffu, s, 4);
                s += __shfl_xor_sync(0xffffffffu, s, 8);
                s += __shfl_xor_sync(0xffffffffu, s, 16);
                if (g == 0) partial[w * NCOL + nt * 8 + q * 2 + j] = s;
            }
        __syncthreads();
        if (tid < NCOL) {
            float tot = 0.0f;
            #pragma unroll
            for (int w2 = 0; w2 < NW; ++w2) tot += partial[w2 * NCOL + tid];
            sInv[tid] = 1.0f / tot;
        }
        __syncthreads();

        // ---- normalize + store output + entropy partials ----
        #pragma unroll
        for (int nt = 0; nt < 4; ++nt)
            #pragma unroll
            for (int j = 0; j < 2; ++j) {
                const int n = nt * 8 + q * 2 + j;
                const int t = (g0 + n) * LCH + tbase;
                const float inv = sInv[n];
                const float p0 = acc[nt][j]     * inv;
                const float p1 = acc[nt][2 + j] * inv;
                if (t < SEQ) {
                    wout[(size_t)t * DIM + m0]     = p0;
                    wout[(size_t)t * DIM + m0 + 8] = p1;
                }
                float e = p0 * __logf(p0 + 1e-10f) + p1 * __logf(p1 + 1e-10f);
                e += __shfl_xor_sync(0xffffffffu, e, 4);
                e += __shfl_xor_sync(0xffffffffu, e, 8);
                e += __shfl_xor_sync(0xffffffffu, e, 16);
                if (g == 0) epart[w * NCOL + n] = e;
            }
        __syncthreads();            // also protects bNxt for next step
        if (tid < NCOL) {
            float e = 0.0f;
            #pragma unroll
            for (int w2 = 0; w2 < NW; ++w2) e += epart[w2 * NCOL + tid];
            const int tg = (g0 + tid) * LCH + tbase;
            if (tg < SEQ) unc[tg] = -e;
        }
    }
}

extern "C" void kernel_launch(void* const* d_in, const int* in_sizes, int n_in,
                              void* d_out, int out_size) {
    const float* probs = (const float*)d_in[0];          // (SEQ, DIM)
    const float* T     = (const float*)d_in[1];          // (DIM, DIM)
    float* out = (float*)d_out;                          // normalized probs
    float* unc = out + (size_t)SEQ * DIM;                // entropy

    cudaFuncSetAttribute(pl_scan_fused, cudaFuncAttributeMaxDynamicSharedMemorySize, SMEM_BYTES);
    pl_scan_fused<<<NCTA, THREADS, SMEM_BYTES>>>(probs, out, unc, T);
}

// round 6
// speedup vs baseline: 10.6505x; 1.0633x over previous
// PriorLayer online belief-propagation scan on GB300 (sm_103a) — fused mma.sync,
// A-in-registers, single-reduction (entropy-algebra) version.
//
// (tcgen05 unavailable: harness compiles via compute_103 virtual arch which
// rejects arch-accelerated PTX. Warp-level mma.sync.m16n8k16 bf16 instead.)
//
// state_t = normalize(diag(p_t) @ T @ state_{t-1}) is scale-invariant -> run
// UNNORMALIZED with fixed 2^-6 rescale. Chain contracts >~5x/step (measured:
// rel_err flat WARM=16..6; theory ~14x) -> 4736 chunks (148 CTAs x 32 cols),
// WARM=5 warmup steps from uniform; chunk 0 exact via forced-uniform t<0.
//
// Per CTA per step: D(256x32) = T(256x256,bf16,regs) @ V(256x32,bf16,smem).
// 16 warps, warp w owns rows 16w..16w+15; T fragments persist in 64 regs.
// Entropy via H = log S - E/S (S = sum v, E = sum v log v, unnormalized) so
// normalization + entropy share ONE reduction: per-warp shfl -> float2
// partials -> 8-threads-per-column parallel combine. Two syncs per output
// step, one per warmup step.

#include <cuda_runtime.h>
#include <cuda_bf16.h>
#include <cstdint>

#define DIM     256
#define SEQ     65536
#define NCTA    148
#define NCOL    32                 // chunk columns per CTA
#define LCH     14                 // output steps per chunk (148*32*14 >= 65536)
#define WARM    5
#define STEPS   (WARM + LCH)       // 19
#define THREADS 512
#define NW      16                 // warps
#define RESC    0.015625f          // 2^-6 cancels expected per-step growth (~64x)

#define PT_B    528                // T smem row stride (prologue only)
#define PV_B    80                 // V smem row stride (32 bf16 + 8 pad)
#define T_BYTES (DIM * PT_B)       // 135168
#define V_BYTES (DIM * PV_B)       // 20480 per buffer
#define RED_OFF (T_BYTES + 2 * V_BYTES)
#define SMEM_BYTES (RED_OFF + NW * NCOL * 8 + NCOL * 4)   // partial2 + sInv

__device__ __forceinline__ uint32_t smem_u32(const void* p) {
    uint32_t a;
    asm("{ .reg .u64 t; cvta.to.shared.u64 t, %1; cvt.u32.u64 %0, t; }" : "=r"(a) : "l"(p));
    return a;
}

#define LDSM_X4(r, addr) \
    asm volatile("ldmatrix.sync.aligned.m8n8.x4.shared.b16 {%0,%1,%2,%3}, [%4];" \
                 : "=r"((r)[0]), "=r"((r)[1]), "=r"((r)[2]), "=r"((r)[3]) : "r"(addr))
#define LDSM_X4_T(r, addr) \
    asm volatile("ldmatrix.sync.aligned.m8n8.x4.trans.shared.b16 {%0,%1,%2,%3}, [%4];" \
                 : "=r"((r)[0]), "=r"((r)[1]), "=r"((r)[2]), "=r"((r)[3]) : "r"(addr))
#define MMA16816(c, a, bb0, bb1) \
    asm volatile("mma.sync.aligned.m16n8k16.row.col.f32.bf16.bf16.f32 " \
                 "{%0,%1,%2,%3}, {%4,%5,%6,%7}, {%8,%9}, {%0,%1,%2,%3};" \
                 : "+f"((c)[0]), "+f"((c)[1]), "+f"((c)[2]), "+f"((c)[3]) \
                 : "r"((a)[0]), "r"((a)[1]), "r"((a)[2]), "r"((a)[3]), "r"(bb0), "r"(bb1))

__global__ __launch_bounds__(THREADS, 1)
void pl_scan_fused(const float* __restrict__ probs, float* __restrict__ wout,
                   float* __restrict__ unc, const float* __restrict__ T) {
    extern __shared__ char sm[];
    char*   Tsm      = sm;                                  // prologue only
    char*   Vsm      = sm + T_BYTES;                        // bf16 V x2 buffers
    float2* partial2 = reinterpret_cast<float2*>(sm + RED_OFF);    // [NW][NCOL] (s,e)
    float*  sInv     = reinterpret_cast<float*>(partial2 + NW * NCOL);   // [NCOL]

    const int tid  = threadIdx.x;
    const int w    = tid >> 5;
    const int lane = tid & 31;
    const int g    = (lane >> 2) & 7;  // row within 8-group
    const int q    = lane & 3;         // col pair
    const int m0   = w * 16 + g;       // this thread's first output row
    const int g0   = blockIdx.x * NCOL;

    // ---- prologue: T fp32 -> bf16 smem (padded rows) ----
    for (int idx = tid; idx < DIM * DIM / 4; idx += THREADS) {
        int e = idx * 4;
        int i = e >> 8;
        int k = e & 255;
        float4 tv = *reinterpret_cast<const float4*>(T + i * DIM + k);
        __nv_bfloat162* dst = reinterpret_cast<__nv_bfloat162*>(Tsm + i * PT_B + k * 2);
        dst[0] = __floats2bfloat162_rn(tv.x, tv.y);
        dst[1] = __floats2bfloat162_rn(tv.z, tv.w);
    }
    for (int idx = tid; idx < V_BYTES / 4; idx += THREADS)
        *reinterpret_cast<uint32_t*>(Vsm + idx * 4) = 0x3F803F80u;   // uniform V0
    __syncthreads();

    // ---- hoist A fragments into persistent registers (T never changes) ----
    const int mloc = ((lane >> 3) & 1) * 8 + (lane & 7);
    const int kofB = (lane >> 4) * 16;
    const uint32_t aBase = smem_u32(Tsm) + (w * 16 + mloc) * PT_B + kofB;
    uint32_t aF[16][4];
    #pragma unroll
    for (int kt = 0; kt < 16; ++kt) LDSM_X4(aF[kt], aBase + kt * 32);

    const uint32_t bOff0 = (uint32_t)(mloc * PV_B + (lane >> 4) * 16);
    const uint32_t bOff1 = bOff0 + 32;
    const uint32_t vBase = smem_u32(Vsm);

    for (int step = 0; step < STEPS; ++step) {
        const int cur   = step & 1;
        const int tbase = step - WARM;
        const uint32_t bCur = vBase + cur * V_BYTES;
        const uint32_t bNxt = vBase + (cur ^ 1) * V_BYTES;

        // ---- observation gather (issues early; consumed after MMA) ----
        float pr[4][2][2];
        #pragma unroll
        for (int nt = 0; nt < 4; ++nt)
            #pragma unroll
            for (int j = 0; j < 2; ++j) {
                int t  = (g0 + nt * 8 + q * 2 + j) * LCH + tbase;
                int tc = min(max(t, 0), SEQ - 1);
                const float* pp = probs + (size_t)tc * DIM + m0;
                pr[nt][j][0] = __ldcg(pp)     * RESC;
                pr[nt][j][1] = __ldcg(pp + 8) * RESC;
            }

        // ---- GEMM: this warp's 16 rows x all 32 cols (A from registers) ----
        float acc[4][4];
        #pragma unroll
        for (int nt = 0; nt < 4; ++nt)
            #pragma unroll
            for (int i = 0; i < 4; ++i) acc[nt][i] = 0.0f;

        #pragma unroll
        for (int kt = 0; kt < 16; ++kt) {
            uint32_t b0[4], b1[4];
            LDSM_X4_T(b0, bCur + bOff0 + kt * 16 * PV_B);
            LDSM_X4_T(b1, bCur + bOff1 + kt * 16 * PV_B);
            MMA16816(acc[0], aF[kt], b0[0], b0[1]);
            MMA16816(acc[1], aF[kt], b0[2], b0[3]);
            MMA16816(acc[2], aF[kt], b1[0], b1[1]);
            MMA16816(acc[3], aF[kt], b1[2], b1[3]);
        }

        // ---- apply observation (in place), write bf16 V for next step ----
        #pragma unroll
        for (int nt = 0; nt < 4; ++nt) {
            const int n0 = nt * 8 + q * 2;
            #pragma unroll
            for (int j = 0; j < 2; ++j) {
                const int t = (g0 + n0 + j) * LCH + tbase;
                float v0 = acc[nt][j]     * pr[nt][j][0];
                float v1 = acc[nt][2 + j] * pr[nt][j][1];
                if (t < 0) { v0 = 1.0f; v1 = 1.0f; }   // chunk 0 pre-window
                acc[nt][j]     = v0;
                acc[nt][2 + j] = v1;
            }
            __nv_bfloat162 lo = __floats2bfloat162_rn(acc[nt][0], acc[nt][1]);
            __nv_bfloat162 hi = __floats2bfloat162_rn(acc[nt][2], acc[nt][3]);
            asm volatile("st.shared.b32 [%0], %1;" ::
                "r"(bNxt + (uint32_t)(m0 * PV_B + n0 * 2)),
                "r"(*reinterpret_cast<uint32_t*>(&lo)));
            asm volatile("st.shared.b32 [%0], %1;" ::
                "r"(bNxt + (uint32_t)((m0 + 8) * PV_B + n0 * 2)),
                "r"(*reinterpret_cast<uint32_t*>(&hi)));
        }

        if (tbase < 0) {            // warmup step: state update only
            __syncthreads();
            continue;
        }

        // ---- ONE fused reduction: per-column S = sum v, E = sum v*log v ----
        #pragma unroll
        for (int nt = 0; nt < 4; ++nt)
            #pragma unroll
            for (int j = 0; j < 2; ++j) {
                const float va = acc[nt][j];
                const float vb = acc[nt][2 + j];
                float s = va + vb;
                float e = va * __logf(fmaxf(va, 1e-35f))
                        + vb * __logf(fmaxf(vb, 1e-35f));
                s += __shfl_xor_sync(0xffffffffu, s, 4);
                e += __shfl_xor_sync(0xffffffffu, e, 4);
                s += __shfl_xor_sync(0xffffffffu, s, 8);
                e += __shfl_xor_sync(0xffffffffu, e, 8);
                s += __shfl_xor_sync(0xffffffffu, s, 16);
                e += __shfl_xor_sync(0xffffffffu, e, 16);
                if (g == 0) partial2[w * NCOL + nt * 8 + q * 2 + j] = make_float2(s, e);
            }
        __syncthreads();

        // parallel cross-warp combine: 8 threads per column (n = tid>>3)
        if (tid < NCOL * 8) {
            const int n = tid >> 3;
            const int i = tid & 7;
            float2 p0 = partial2[(2 * i)     * NCOL + n];
            float2 p1 = partial2[(2 * i + 1) * NCOL + n];
            float s = p0.x + p1.x;
            float e = p0.y + p1.y;
            s += __shfl_xor_sync(0xffffffffu, s, 1);
            e += __shfl_xor_sync(0xffffffffu, e, 1);
            s += __shfl_xor_sync(0xffffffffu, s, 2);
            e += __shfl_xor_sync(0xffffffffu, e, 2);
            s += __shfl_xor_sync(0xffffffffu, s, 4);
            e += __shfl_xor_sync(0xffffffffu, e, 4);
            if (i == 0) {
                sInv[n] = 1.0f / s;
                const int tg = (g0 + n) * LCH + tbase;
                if (tg < SEQ) unc[tg] = __logf(s) - e / s;   // H = log S - E/S
            }
        }
        __syncthreads();

        // ---- normalize + store output ----
        #pragma unroll
        for (int nt = 0; nt < 4; ++nt)
            #pragma unroll
            for (int j = 0; j < 2; ++j) {
                const int n = nt * 8 + q * 2 + j;
                const int t = (g0 + n) * LCH + tbase;
                const float inv = sInv[n];                  // LDS broadcast
                if (t < SEQ) {
                    wout[(size_t)t * DIM + m0]     = acc[nt][j]     * inv;
                    wout[(size_t)t * DIM + m0 + 8] = acc[nt][2 + j] * inv;
                }
            }
        // NOTE: no extra sync needed here — the sync at the top of the next
        // step's reduction (or the warmup sync) orders bNxt reuse; but the
        // next step's STS into bCur must not pass our LDSM reads, which the
        // second __syncthreads above already ordered. The normalize loop only
        // reads sInv (written before that sync) and registers.
    }
}

extern "C" void kernel_launch(void* const* d_in, const int* in_sizes, int n_in,
                              void* d_out, int out_size) {
    const float* probs = (const float*)d_in[0];          // (SEQ, DIM)
    const float* T     = (const float*)d_in[1];          // (DIM, DIM)
    float* out = (float*)d_out;                          // normalized probs
    float* unc = out + (size_t)SEQ * DIM;                // entropy

    cudaFuncSetAttribute(pl_scan_fused, cudaFuncAttributeMaxDynamicSharedMemorySize, SMEM_BYTES);
    pl_scan_fused<<<NCTA, THREADS, SMEM_BYTES>>>(probs, out, unc, T);
}

// round 7
// speedup vs baseline: 12.9685x; 1.2176x over previous
// PriorLayer online belief-propagation scan on GB300 (sm_103a) — fused mma.sync,
// A-in-registers, smem-staged coalesced P, single-reduction version.
//
// (tcgen05 unavailable: harness compiles via compute_103 virtual arch which
// rejects arch-accelerated PTX. Warp-level mma.sync.m16n8k16 bf16 instead.)
//
// state_t = normalize(diag(p_t) @ T @ state_{t-1}) is scale-invariant -> run
// UNNORMALIZED with fixed 2^-6 rescale; entropy via H = log S - E/S on the
// unnormalized vector so normalization+entropy share one reduction.
// Chain contracts >~5x/step -> 4736 chunks (148 CTAs x 32 cols), WARM=4
// warmup steps from uniform; chunk 0 exact via forced-uniform t<0.
//
// Per CTA per step: D(256x32) = T(256x256,bf16,regs) @ V(256x32,bf16,smem).
// 16 warps, warp w owns rows 16w..16w+15; T fragments persist in 64 regs.
// Observation rows are PREFETCHED one step ahead into smem by coalesced
// LDG.128 (warp w loads rows 2w,2w+1), STS placed after the MMA loop so the
// global latency hides behind the GEMM; epilogue reads them via LDS.
// B fragments double-buffered across k-tiles for ILP.

#include <cuda_runtime.h>
#include <cuda_bf16.h>
#include <cstdint>

#define DIM     256
#define SEQ     65536
#define NCTA    148
#define NCOL    32                 // chunk columns per CTA
#define LCH     14                 // output steps per chunk (148*32*14 >= 65536)
#define WARM    4
#define STEPS   (WARM + LCH)       // 18
#define THREADS 512
#define NW      16                 // warps
#define RESC    0.015625f          // 2^-6 cancels expected per-step growth (~64x)

#define PT_B    528                // T smem row stride (prologue only)
#define PV_B    80                 // V smem row stride (32 bf16 + 8 pad)
#define T_BYTES (DIM * PT_B)       // 135168 (reused as P staging after prologue)
#define PROW_B  1056               // P row stride: 256 floats + 32B pad
#define PBUF_B  (NCOL * PROW_B)    // 33792 per buffer (x2 = 67584 <= T_BYTES)
#define V_BYTES (DIM * PV_B)       // 20480 per buffer
#define RED_OFF (T_BYTES + 2 * V_BYTES)
#define SMEM_BYTES (RED_OFF + NW * NCOL * 8 + NCOL * 4)   // partial2 + sInv

__device__ __forceinline__ uint32_t smem_u32(const void* p) {
    uint32_t a;
    asm("{ .reg .u64 t; cvta.to.shared.u64 t, %1; cvt.u32.u64 %0, t; }" : "=r"(a) : "l"(p));
    return a;
}

#define LDSM_X4(r, addr) \
    asm volatile("ldmatrix.sync.aligned.m8n8.x4.shared.b16 {%0,%1,%2,%3}, [%4];" \
                 : "=r"((r)[0]), "=r"((r)[1]), "=r"((r)[2]), "=r"((r)[3]) : "r"(addr))
#define LDSM_X4_T(r, addr) \
    asm volatile("ldmatrix.sync.aligned.m8n8.x4.trans.shared.b16 {%0,%1,%2,%3}, [%4];" \
                 : "=r"((r)[0]), "=r"((r)[1]), "=r"((r)[2]), "=r"((r)[3]) : "r"(addr))
#define MMA16816(c, a, bb0, bb1) \
    asm volatile("mma.sync.aligned.m16n8k16.row.col.f32.bf16.bf16.f32 " \
                 "{%0,%1,%2,%3}, {%4,%5,%6,%7}, {%8,%9}, {%0,%1,%2,%3};" \
                 : "+f"((c)[0]), "+f"((c)[1]), "+f"((c)[2]), "+f"((c)[3]) \
                 : "r"((a)[0]), "r"((a)[1]), "r"((a)[2]), "r"((a)[3]), "r"(bb0), "r"(bb1))

__global__ __launch_bounds__(THREADS, 1)
void pl_scan_fused(const float* __restrict__ probs, float* __restrict__ wout,
                   float* __restrict__ unc, const float* __restrict__ T) {
    extern __shared__ char sm[];
    char*   Tsm      = sm;                                  // prologue; then P staging
    char*   Vsm      = sm + T_BYTES;                        // bf16 V x2 buffers
    float2* partial2 = reinterpret_cast<float2*>(sm + RED_OFF);    // [NW][NCOL] (s,e)
    float*  sInv     = reinterpret_cast<float*>(partial2 + NW * NCOL);   // [NCOL]

    const int tid  = threadIdx.x;
    const int w    = tid >> 5;
    const int lane = tid & 31;
    const int g    = (lane >> 2) & 7;  // row within 8-group
    const int q    = lane & 3;         // col pair
    const int m0   = w * 16 + g;       // this thread's first output row
    const int g0   = blockIdx.x * NCOL;

    // ---- prologue: T fp32 -> bf16 smem (padded rows) ----
    for (int idx = tid; idx < DIM * DIM / 4; idx += THREADS) {
        int e = idx * 4;
        int i = e >> 8;
        int k = e & 255;
        float4 tv = *reinterpret_cast<const float4*>(T + i * DIM + k);
        __nv_bfloat162* dst = reinterpret_cast<__nv_bfloat162*>(Tsm + i * PT_B + k * 2);
        dst[0] = __floats2bfloat162_rn(tv.x, tv.y);
        dst[1] = __floats2bfloat162_rn(tv.z, tv.w);
    }
    for (int idx = tid; idx < V_BYTES / 4; idx += THREADS)
        *reinterpret_cast<uint32_t*>(Vsm + idx * 4) = 0x3F803F80u;   // uniform V0
    __syncthreads();

    // ---- hoist A fragments into persistent registers (T never changes) ----
    const int mloc = ((lane >> 3) & 1) * 8 + (lane & 7);
    const int kofB = (lane >> 4) * 16;
    const uint32_t aBaseT = smem_u32(Tsm) + (w * 16 + mloc) * PT_B + kofB;
    uint32_t aF[16][4];
    #pragma unroll
    for (int kt = 0; kt < 16; ++kt) LDSM_X4(aF[kt], aBaseT + kt * 32);
    __syncthreads();               // all A hoists done before Tsm is reused for P

    const uint32_t bOff0 = (uint32_t)(mloc * PV_B + (lane >> 4) * 16);
    const uint32_t bOff1 = bOff0 + 32;
    const uint32_t vBase = smem_u32(Vsm);
    const uint32_t pBase = smem_u32(Tsm);   // P staging overlays Tsm

    // P prefetch addressing: warp w loads rows 2w, 2w+1 (each 256 floats);
    // per row: 32 lanes x 2 float4.
    const int prRow0 = 2 * w;
    // ---- preload P for step 0 into buffer 0 ----
    {
        #pragma unroll
        for (int r = 0; r < 2; ++r) {
            const int n  = prRow0 + r;
            int t  = (g0 + n) * LCH + (0 - WARM);
            int tc = min(max(t, 0), SEQ - 1);
            const float4* src = reinterpret_cast<const float4*>(probs + (size_t)tc * DIM);
            float4 v0 = __ldcg(src + lane);
            float4 v1 = __ldcg(src + lane + 32);
            float4* dst = reinterpret_cast<float4*>(sm + (pBase - smem_u32(sm)) + n * PROW_B);
            dst[lane]      = v0;
            dst[lane + 32] = v1;
        }
    }
    __syncthreads();

    for (int step = 0; step < STEPS; ++step) {
        const int cur   = step & 1;
        const int tbase = step - WARM;
        const uint32_t bCur = vBase + cur * V_BYTES;
        const uint32_t bNxt = vBase + (cur ^ 1) * V_BYTES;
        const uint32_t pCur = pBase + (uint32_t)cur * PBUF_B;
        const uint32_t pNxt = pBase + (uint32_t)(cur ^ 1) * PBUF_B;

        // ---- issue next step's P loads (coalesced LDG.128; STS deferred) ----
        float4 pf[2][2];
        const bool doPf = (step + 1 < STEPS);
        if (doPf) {
            #pragma unroll
            for (int r = 0; r < 2; ++r) {
                const int n  = prRow0 + r;
                int t  = (g0 + n) * LCH + (tbase + 1);
                int tc = min(max(t, 0), SEQ - 1);
                const float4* src = reinterpret_cast<const float4*>(probs + (size_t)tc * DIM);
                pf[r][0] = __ldcg(src + lane);
                pf[r][1] = __ldcg(src + lane + 32);
            }
        }

        // ---- GEMM: this warp's 16 rows x all 32 cols (A regs, B pipelined) ----
        float acc[4][4];
        #pragma unroll
        for (int nt = 0; nt < 4; ++nt)
            #pragma unroll
            for (int i = 0; i < 4; ++i) acc[nt][i] = 0.0f;

        uint32_t b0[2][4], b1[2][4];
        LDSM_X4_T(b0[0], bCur + bOff0);
        LDSM_X4_T(b1[0], bCur + bOff1);
        #pragma unroll
        for (int kt = 0; kt < 16; ++kt) {
            const int cb = kt & 1, nb = cb ^ 1;
            if (kt < 15) {
                LDSM_X4_T(b0[nb], bCur + bOff0 + (kt + 1) * 16 * PV_B);
                LDSM_X4_T(b1[nb], bCur + bOff1 + (kt + 1) * 16 * PV_B);
            }
            MMA16816(acc[0], aF[kt], b0[cb][0], b0[cb][1]);
            MMA16816(acc[1], aF[kt], b0[cb][2], b0[cb][3]);
            MMA16816(acc[2], aF[kt], b1[cb][0], b1[cb][1]);
            MMA16816(acc[3], aF[kt], b1[cb][2], b1[cb][3]);
        }

        // ---- park prefetched P rows in smem (LDG latency now covered) ----
        if (doPf) {
            #pragma unroll
            for (int r = 0; r < 2; ++r) {
                const uint32_t dst = pNxt + (uint32_t)(prRow0 + r) * PROW_B + lane * 16;
                asm volatile("st.shared.v4.b32 [%0], {%1,%2,%3,%4};" ::
                    "r"(dst), "r"(__float_as_uint(pf[r][0].x)), "r"(__float_as_uint(pf[r][0].y)),
                    "r"(__float_as_uint(pf[r][0].z)), "r"(__float_as_uint(pf[r][0].w)));
                asm volatile("st.shared.v4.b32 [%0], {%1,%2,%3,%4};" ::
                    "r"(dst + 512), "r"(__float_as_uint(pf[r][1].x)), "r"(__float_as_uint(pf[r][1].y)),
                    "r"(__float_as_uint(pf[r][1].z)), "r"(__float_as_uint(pf[r][1].w)));
            }
        }

        // ---- apply observation from smem P; write bf16 V for next step ----
        #pragma unroll
        for (int nt = 0; nt < 4; ++nt) {
            const int n0 = nt * 8 + q * 2;
            #pragma unroll
            for (int j = 0; j < 2; ++j) {
                const int n = n0 + j;
                const int t = (g0 + n) * LCH + tbase;
                float pa, pb;
                asm volatile("ld.shared.f32 %0, [%1];" : "=f"(pa)
                             : "r"(pCur + (uint32_t)(n * PROW_B + m0 * 4)));
                asm volatile("ld.shared.f32 %0, [%1];" : "=f"(pb)
                             : "r"(pCur + (uint32_t)(n * PROW_B + (m0 + 8) * 4)));
                float v0 = acc[nt][j]     * (pa * RESC);
                float v1 = acc[nt][2 + j] * (pb * RESC);
                if (t < 0) { v0 = 1.0f; v1 = 1.0f; }   // chunk 0 pre-window
                acc[nt][j]     = v0;
                acc[nt][2 + j] = v1;
            }
            __nv_bfloat162 lo = __floats2bfloat162_rn(acc[nt][0], acc[nt][1]);
            __nv_bfloat162 hi = __floats2bfloat162_rn(acc[nt][2], acc[nt][3]);
            asm volatile("st.shared.b32 [%0], %1;" ::
                "r"(bNxt + (uint32_t)(m0 * PV_B + n0 * 2)),
                "r"(*reinterpret_cast<uint32_t*>(&lo)));
            asm volatile("st.shared.b32 [%0], %1;" ::
                "r"(bNxt + (uint32_t)((m0 + 8) * PV_B + n0 * 2)),
                "r"(*reinterpret_cast<uint32_t*>(&hi)));
        }

        if (tbase < 0) {            // warmup step: state update only
            __syncthreads();
            continue;
        }

        // ---- ONE fused reduction: per-column S = sum v, E = sum v*log v ----
        #pragma unroll
        for (int nt = 0; nt < 4; ++nt)
            #pragma unroll
            for (int j = 0; j < 2; ++j) {
                const float va = acc[nt][j];
                const float vb = acc[nt][2 + j];
                float s = va + vb;
                float e = va * __logf(fmaxf(va, 1e-35f))
                        + vb * __logf(fmaxf(vb, 1e-35f));
                s += __shfl_xor_sync(0xffffffffu, s, 4);
                e += __shfl_xor_sync(0xffffffffu, e, 4);
                s += __shfl_xor_sync(0xffffffffu, s, 8);
                e += __shfl_xor_sync(0xffffffffu, e, 8);
                s += __shfl_xor_sync(0xffffffffu, s, 16);
                e += __shfl_xor_sync(0xffffffffu, e, 16);
                if (g == 0) partial2[w * NCOL + nt * 8 + q * 2 + j] = make_float2(s, e);
            }
        __syncthreads();

        // parallel cross-warp combine: 8 threads per column (n = tid>>3)
        if (tid < NCOL * 8) {
            const int n = tid >> 3;
            const int i = tid & 7;
            float2 c0 = partial2[(2 * i)     * NCOL + n];
            float2 c1 = partial2[(2 * i + 1) * NCOL + n];
            float s = c0.x + c1.x;
            float e = c0.y + c1.y;
            s += __shfl_xor_sync(0xffffffffu, s, 1);
            e += __shfl_xor_sync(0xffffffffu, e, 1);
            s += __shfl_xor_sync(0xffffffffu, s, 2);
            e += __shfl_xor_sync(0xffffffffu, e, 2);
            s += __shfl_xor_sync(0xffffffffu, s, 4);
            e += __shfl_xor_sync(0xffffffffu, e, 4);
            if (i == 0) {
                sInv[n] = 1.0f / s;
                const int tg = (g0 + n) * LCH + tbase;
                if (tg < SEQ) unc[tg] = __logf(s) - e / s;   // H = log S - E/S
            }
        }
        __syncthreads();

        // ---- normalize + store output ----
        #pragma unroll
        for (int nt = 0; nt < 4; ++nt)
            #pragma unroll
            for (int j = 0; j < 2; ++j) {
                const int n = nt * 8 + q * 2 + j;
                const int t = (g0 + n) * LCH + tbase;
                const float inv = sInv[n];
                if (t < SEQ) {
                    wout[(size_t)t * DIM + m0]     = acc[nt][j]     * inv;
                    wout[(size_t)t * DIM + m0 + 8] = acc[nt][2 + j] * inv;
                }
            }
        // Ordering: this step's smem reads (V LDSM, P LDS, partial2) all precede
        // the two syncs above; next step's writes into those buffers come after
        // them in every thread's program order.
    }
}

extern "C" void kernel_launch(void* const* d_in, const int* in_sizes, int n_in,
                              void* d_out, int out_size) {
    const float* probs = (const float*)d_in[0];          // (SEQ, DIM)
    const float* T     = (const float*)d_in[1];          // (DIM, DIM)
    float* out = (float*)d_out;                          // normalized probs
    float* unc = out + (size_t)SEQ * DIM;                // entropy

    cudaFuncSetAttribute(pl_scan_fused, cudaFuncAttributeMaxDynamicSharedMemorySize, SMEM_BYTES);
    pl_scan_fused<<<NCTA, THREADS, SMEM_BYTES>>>(probs, out, unc, T);
}

// round 8
// speedup vs baseline: 13.0699x; 1.0078x over previous
// PriorLayer online belief-propagation scan on GB300 (sm_103a) — fused mma.sync,
// A-in-registers, smem-staged coalesced P, fp16 operands, single-reduction.
//
// (tcgen05 unavailable: harness compiles via compute_103 virtual arch which
// rejects arch-accelerated PTX. Warp-level mma.sync.m16n8k16 f16 instead.)
//
// state_t = normalize(diag(p_t) @ T @ state_{t-1}) is scale-invariant -> run
// UNNORMALIZED with fixed 2^-6 rescale; entropy via H = log S - E/S on the
// unnormalized vector so normalization+entropy share one reduction.
// Chain contracts ~14x/step -> 4736 chunks (148 CTAs x 32 cols), WARM=3
// warmup steps from uniform; chunk 0 exact via forced-uniform t<0.
// T/V quantized to fp16 (10 mantissa bits; ~8x less noise than bf16) — the
// fp16 range is safe because the 2^-6 rescale pins sum(v) ~ 256, v in [0,~2].
//
// Per CTA per step: D(256x32) = T(256x256,f16,regs) @ V(256x32,f16,smem).
// 16 warps, warp w owns rows 16w..16w+15; T fragments persist in 64 regs.
// Observation rows prefetched one step ahead via coalesced LDG.128 into smem
// (STS parked after the MMA loop so global latency hides behind the GEMM);
// epilogue LDS is bank-conflict-free (P row stride 1040B: 260 % 32 = 4 ->
// bank = 8q+g+c, a 32-permutation). B fragments double-buffered across k.

#include <cuda_runtime.h>
#include <cuda_fp16.h>
#include <cstdint>

#define DIM     256
#define SEQ     65536
#define NCTA    148
#define NCOL    32                 // chunk columns per CTA
#define LCH     14                 // output steps per chunk (148*32*14 >= 65536)
#define WARM    3
#define STEPS   (WARM + LCH)       // 17
#define THREADS 512
#define NW      16                 // warps
#define RESC    0.015625f          // 2^-6 cancels expected per-step growth (~64x)

#define PT_B    528                // T smem row stride (prologue only)
#define PV_B    80                 // V smem row stride (32 f16 + 8 pad)
#define T_BYTES (DIM * PT_B)       // 135168 (reused as P staging after prologue)
#define PROW_B  1040               // P row stride: 256 floats + 16B pad (260%32=4)
#define PBUF_B  (NCOL * PROW_B)    // 33280 per buffer (x2 = 66560 <= T_BYTES)
#define V_BYTES (DIM * PV_B)       // 20480 per buffer
#define RED_OFF (T_BYTES + 2 * V_BYTES)
#define SMEM_BYTES (RED_OFF + NW * NCOL * 8 + NCOL * 4)   // partial2 + sInv

__device__ __forceinline__ uint32_t smem_u32(const void* p) {
    uint32_t a;
    asm("{ .reg .u64 t; cvta.to.shared.u64 t, %1; cvt.u32.u64 %0, t; }" : "=r"(a) : "l"(p));
    return a;
}

#define LDSM_X4(r, addr) \
    asm volatile("ldmatrix.sync.aligned.m8n8.x4.shared.b16 {%0,%1,%2,%3}, [%4];" \
                 : "=r"((r)[0]), "=r"((r)[1]), "=r"((r)[2]), "=r"((r)[3]) : "r"(addr))
#define LDSM_X4_T(r, addr) \
    asm volatile("ldmatrix.sync.aligned.m8n8.x4.trans.shared.b16 {%0,%1,%2,%3}, [%4];" \
                 : "=r"((r)[0]), "=r"((r)[1]), "=r"((r)[2]), "=r"((r)[3]) : "r"(addr))
#define MMA16816(c, a, bb0, bb1) \
    asm volatile("mma.sync.aligned.m16n8k16.row.col.f32.f16.f16.f32 " \
                 "{%0,%1,%2,%3}, {%4,%5,%6,%7}, {%8,%9}, {%0,%1,%2,%3};" \
                 : "+f"((c)[0]), "+f"((c)[1]), "+f"((c)[2]), "+f"((c)[3]) \
                 : "r"((a)[0]), "r"((a)[1]), "r"((a)[2]), "r"((a)[3]), "r"(bb0), "r"(bb1))

__global__ __launch_bounds__(THREADS, 1)
void pl_scan_fused(const float* __restrict__ probs, float* __restrict__ wout,
                   float* __restrict__ unc, const float* __restrict__ T) {
    extern __shared__ char sm[];
    char*   Tsm      = sm;                                  // prologue; then P staging
    char*   Vsm      = sm + T_BYTES;                        // f16 V x2 buffers
    float2* partial2 = reinterpret_cast<float2*>(sm + RED_OFF);    // [NW][NCOL] (s,e)
    float*  sInv     = reinterpret_cast<float*>(partial2 + NW * NCOL);   // [NCOL]

    const int tid  = threadIdx.x;
    const int w    = tid >> 5;
    const int lane = tid & 31;
    const int g    = (lane >> 2) & 7;  // row within 8-group
    const int q    = lane & 3;         // col pair
    const int m0   = w * 16 + g;       // this thread's first output row
    const int g0   = blockIdx.x * NCOL;

    // ---- prologue: T fp32 -> fp16 smem (padded rows) ----
    for (int idx = tid; idx < DIM * DIM / 4; idx += THREADS) {
        int e = idx * 4;
        int i = e >> 8;
        int k = e & 255;
        float4 tv = *reinterpret_cast<const float4*>(T + i * DIM + k);
        __half2* dst = reinterpret_cast<__half2*>(Tsm + i * PT_B + k * 2);
        dst[0] = __floats2half2_rn(tv.x, tv.y);
        dst[1] = __floats2half2_rn(tv.z, tv.w);
    }
    for (int idx = tid; idx < V_BYTES / 4; idx += THREADS)
        *reinterpret_cast<uint32_t*>(Vsm + idx * 4) = 0x3C003C00u;   // uniform V0 (f16 1.0)
    __syncthreads();

    // ---- hoist A fragments into persistent registers (T never changes) ----
    const int mloc = ((lane >> 3) & 1) * 8 + (lane & 7);
    const int kofB = (lane >> 4) * 16;
    const uint32_t aBaseT = smem_u32(Tsm) + (w * 16 + mloc) * PT_B + kofB;
    uint32_t aF[16][4];
    #pragma unroll
    for (int kt = 0; kt < 16; ++kt) LDSM_X4(aF[kt], aBaseT + kt * 32);
    __syncthreads();               // all A hoists done before Tsm is reused for P

    const uint32_t bOff0 = (uint32_t)(mloc * PV_B + (lane >> 4) * 16);
    const uint32_t bOff1 = bOff0 + 32;
    const uint32_t vBase = smem_u32(Vsm);
    const uint32_t pBase = smem_u32(Tsm);   // P staging overlays Tsm

    // P prefetch addressing: warp w loads rows 2w, 2w+1 (each 256 floats).
    const int prRow0 = 2 * w;
    // ---- preload P for step 0 into buffer 0 ----
    {
        #pragma unroll
        for (int r = 0; r < 2; ++r) {
            const int n  = prRow0 + r;
            int t  = (g0 + n) * LCH + (0 - WARM);
            int tc = min(max(t, 0), SEQ - 1);
            const float4* src = reinterpret_cast<const float4*>(probs + (size_t)tc * DIM);
            float4 v0 = __ldcg(src + lane);
            float4 v1 = __ldcg(src + lane + 32);
            const uint32_t dst = pBase + (uint32_t)(n * PROW_B) + lane * 16;
            asm volatile("st.shared.v4.b32 [%0], {%1,%2,%3,%4};" ::
                "r"(dst), "r"(__float_as_uint(v0.x)), "r"(__float_as_uint(v0.y)),
                "r"(__float_as_uint(v0.z)), "r"(__float_as_uint(v0.w)));
            asm volatile("st.shared.v4.b32 [%0], {%1,%2,%3,%4};" ::
                "r"(dst + 512), "r"(__float_as_uint(v1.x)), "r"(__float_as_uint(v1.y)),
                "r"(__float_as_uint(v1.z)), "r"(__float_as_uint(v1.w)));
        }
    }
    __syncthreads();

    for (int step = 0; step < STEPS; ++step) {
        const int cur   = step & 1;
        const int tbase = step - WARM;
        const uint32_t bCur = vBase + cur * V_BYTES;
        const uint32_t bNxt = vBase + (cur ^ 1) * V_BYTES;
        const uint32_t pCur = pBase + (uint32_t)cur * PBUF_B;
        const uint32_t pNxt = pBase + (uint32_t)(cur ^ 1) * PBUF_B;

        // ---- issue next step's P loads (coalesced LDG.128; STS deferred) ----
        float4 pf[2][2];
        const bool doPf = (step + 1 < STEPS);
        if (doPf) {
            #pragma unroll
            for (int r = 0; r < 2; ++r) {
                const int n  = prRow0 + r;
                int t  = (g0 + n) * LCH + (tbase + 1);
                int tc = min(max(t, 0), SEQ - 1);
                const float4* src = reinterpret_cast<const float4*>(probs + (size_t)tc * DIM);
                pf[r][0] = __ldcg(src + lane);
                pf[r][1] = __ldcg(src + lane + 32);
            }
        }

        // ---- GEMM: this warp's 16 rows x all 32 cols (A regs, B pipelined) ----
        float acc[4][4];
        #pragma unroll
        for (int nt = 0; nt < 4; ++nt)
            #pragma unroll
            for (int i = 0; i < 4; ++i) acc[nt][i] = 0.0f;

        uint32_t b0[2][4], b1[2][4];
        LDSM_X4_T(b0[0], bCur + bOff0);
        LDSM_X4_T(b1[0], bCur + bOff1);
        #pragma unroll
        for (int kt = 0; kt < 16; ++kt) {
            const int cb = kt & 1, nb = cb ^ 1;
            if (kt < 15) {
                LDSM_X4_T(b0[nb], bCur + bOff0 + (kt + 1) * 16 * PV_B);
                LDSM_X4_T(b1[nb], bCur + bOff1 + (kt + 1) * 16 * PV_B);
            }
            MMA16816(acc[0], aF[kt], b0[cb][0], b0[cb][1]);
            MMA16816(acc[1], aF[kt], b0[cb][2], b0[cb][3]);
            MMA16816(acc[2], aF[kt], b1[cb][0], b1[cb][1]);
            MMA16816(acc[3], aF[kt], b1[cb][2], b1[cb][3]);
        }

        // ---- park prefetched P rows in smem (LDG latency now covered) ----
        if (doPf) {
            #pragma unroll
            for (int r = 0; r < 2; ++r) {
                const uint32_t dst = pNxt + (uint32_t)(prRow0 + r) * PROW_B + lane * 16;
                asm volatile("st.shared.v4.b32 [%0], {%1,%2,%3,%4};" ::
                    "r"(dst), "r"(__float_as_uint(pf[r][0].x)), "r"(__float_as_uint(pf[r][0].y)),
                    "r"(__float_as_uint(pf[r][0].z)), "r"(__float_as_uint(pf[r][0].w)));
                asm volatile("st.shared.v4.b32 [%0], {%1,%2,%3,%4};" ::
                    "r"(dst + 512), "r"(__float_as_uint(pf[r][1].x)), "r"(__float_as_uint(pf[r][1].y)),
                    "r"(__float_as_uint(pf[r][1].z)), "r"(__float_as_uint(pf[r][1].w)));
            }
        }

        // ---- apply observation from smem P; write f16 V for next step ----
        #pragma unroll
        for (int nt = 0; nt < 4; ++nt) {
            const int n0 = nt * 8 + q * 2;
            #pragma unroll
            for (int j = 0; j < 2; ++j) {
                const int n = n0 + j;
                const int t = (g0 + n) * LCH + tbase;
                float pa, pb;
                asm volatile("ld.shared.f32 %0, [%1];" : "=f"(pa)
                             : "r"(pCur + (uint32_t)(n * PROW_B + m0 * 4)));
                asm volatile("ld.shared.f32 %0, [%1];" : "=f"(pb)
                             : "r"(pCur + (uint32_t)(n * PROW_B + (m0 + 8) * 4)));
                float v0 = acc[nt][j]     * (pa * RESC);
                float v1 = acc[nt][2 + j] * (pb * RESC);
                if (t < 0) { v0 = 1.0f; v1 = 1.0f; }   // chunk 0 pre-window
                acc[nt][j]     = v0;
                acc[nt][2 + j] = v1;
            }
            __half2 lo = __floats2half2_rn(acc[nt][0], acc[nt][1]);
            __half2 hi = __floats2half2_rn(acc[nt][2], acc[nt][3]);
            asm volatile("st.shared.b32 [%0], %1;" ::
                "r"(bNxt + (uint32_t)(m0 * PV_B + n0 * 2)),
                "r"(*reinterpret_cast<uint32_t*>(&lo)));
            asm volatile("st.shared.b32 [%0], %1;" ::
                "r"(bNxt + (uint32_t)((m0 + 8) * PV_B + n0 * 2)),
                "r"(*reinterpret_cast<uint32_t*>(&hi)));
        }

        if (tbase < 0) {            // warmup step: state update only
            __syncthreads();
            continue;
        }

        // ---- ONE fused reduction: per-column S = sum v, E = sum v*log v ----
        #pragma unroll
        for (int nt = 0; nt < 4; ++nt)
            #pragma unroll
            for (int j = 0; j < 2; ++j) {
                const float va = acc[nt][j];
                const float vb = acc[nt][2 + j];
                float s = va + vb;
                float e = va * __logf(fmaxf(va, 1e-35f))
                        + vb * __logf(fmaxf(vb, 1e-35f));
                s += __shfl_xor_sync(0xffffffffu, s, 4);
                e += __shfl_xor_sync(0xffffffffu, e, 4);
                s += __shfl_xor_sync(0xffffffffu, s, 8);
                e += __shfl_xor_sync(0xffffffffu, e, 8);
                s += __shfl_xor_sync(0xffffffffu, s, 16);
                e += __shfl_xor_sync(0xffffffffu, e, 16);
                if (g == 0) partial2[w * NCOL + nt * 8 + q * 2 + j] = make_float2(s, e);
            }
        __syncthreads();

        // parallel cross-warp combine: 8 threads per column (n = tid>>3)
        if (tid < NCOL * 8) {
            const int n = tid >> 3;
            const int i = tid & 7;
            float2 c0 = partial2[(2 * i)     * NCOL + n];
            float2 c1 = partial2[(2 * i + 1) * NCOL + n];
            float s = c0.x + c1.x;
            float e = c0.y + c1.y;
            s += __shfl_xor_sync(0xffffffffu, s, 1);
            e += __shfl_xor_sync(0xffffffffu, e, 1);
            s += __shfl_xor_sync(0xffffffffu, s, 2);
            e += __shfl_xor_sync(0xffffffffu, e, 2);
            s += __shfl_xor_sync(0xffffffffu, s, 4);
            e += __shfl_xor_sync(0xffffffffu, e, 4);
            if (i == 0) {
                sInv[n] = 1.0f / s;
                const int tg = (g0 + n) * LCH + tbase;
                if (tg < SEQ) unc[tg] = __logf(s) - e / s;   // H = log S - E/S
            }
        }
        __syncthreads();

        // ---- normalize + store output ----
        #pragma unroll
        for (int nt = 0; nt < 4; ++nt)
            #pragma unroll
            for (int j = 0; j < 2; ++j) {
                const int n = nt * 8 + q * 2 + j;
                const int t = (g0 + n) * LCH + tbase;
                const float inv = sInv[n];
                if (t < SEQ) {
                    wout[(size_t)t * DIM + m0]     = acc[nt][j]     * inv;
                    wout[(size_t)t * DIM + m0 + 8] = acc[nt][2 + j] * inv;
                }
            }
        // Ordering: this step's smem reads (V LDSM, P LDS, partial2) all precede
        // the two syncs above; next step's writes into those buffers come after
        // them in every thread's program order.
    }
}

extern "C" void kernel_launch(void* const* d_in, const int* in_sizes, int n_in,
                              void* d_out, int out_size) {
    const float* probs = (const float*)d_in[0];          // (SEQ, DIM)
    const float* T     = (const float*)d_in[1];          // (DIM, DIM)
    float* out = (float*)d_out;                          // normalized probs
    float* unc = out + (size_t)SEQ * DIM;                // entropy

    cudaFuncSetAttribute(pl_scan_fused, cudaFuncAttributeMaxDynamicSharedMemorySize, SMEM_BYTES);
    pl_scan_fused<<<NCTA, THREADS, SMEM_BYTES>>>(probs, out, unc, T);
}